// round 1
// baseline (speedup 1.0000x reference)
#include <cuda_runtime.h>
#include <cuda_bf16.h>

// mean_{i,j} (x[j]-x[i])^2  ==  2*E[x^2] - 2*(E[x])^2
// N = 16384 floats (64 KB). Single-block two-moment reduction.

#define NTHREADS 512

__global__ __launch_bounds__(NTHREADS, 1)
void EditLoss_55525337203377_kernel(const float* __restrict__ x, float* __restrict__ out, int n) {
    // n = 16384, NTHREADS = 512 -> 32 floats per thread = 8 float4 per thread.
    const int tid = threadIdx.x;
    const float4* x4 = reinterpret_cast<const float4*>(x);
    const int n4 = n >> 2;  // 4096 float4

    float s = 0.0f;   // sum x
    float s2 = 0.0f;  // sum x^2

    #pragma unroll 8
    for (int i = tid; i < n4; i += NTHREADS) {
        float4 v = x4[i];
        s  += v.x + v.y + v.z + v.w;
        s2 += v.x * v.x + v.y * v.y + v.z * v.z + v.w * v.w;
    }

    // warp reduction
    #pragma unroll
    for (int off = 16; off > 0; off >>= 1) {
        s  += __shfl_xor_sync(0xFFFFFFFFu, s,  off);
        s2 += __shfl_xor_sync(0xFFFFFFFFu, s2, off);
    }

    __shared__ float sh_s[NTHREADS / 32];
    __shared__ float sh_s2[NTHREADS / 32];
    const int wid = tid >> 5;
    const int lid = tid & 31;
    if (lid == 0) {
        sh_s[wid] = s;
        sh_s2[wid] = s2;
    }
    __syncthreads();

    if (wid == 0) {
        const int nw = NTHREADS / 32;  // 16
        float a  = (lid < nw) ? sh_s[lid]  : 0.0f;
        float a2 = (lid < nw) ? sh_s2[lid] : 0.0f;
        #pragma unroll
        for (int off = 8; off > 0; off >>= 1) {
            a  += __shfl_xor_sync(0xFFFFFFFFu, a,  off);
            a2 += __shfl_xor_sync(0xFFFFFFFFu, a2, off);
        }
        if (lid == 0) {
            float inv_n = 1.0f / (float)n;
            float mean  = a * inv_n;
            float m2    = a2 * inv_n;
            out[0] = 2.0f * (m2 - mean * mean);
        }
    }
}

extern "C" void kernel_launch(void* const* d_in, const int* in_sizes, int n_in,
                              void* d_out, int out_size) {
    const float* x = (const float*)d_in[0];
    float* out = (float*)d_out;
    int n = in_sizes[0];
    EditLoss_55525337203377_kernel<<<1, NTHREADS>>>(x, out, n);
}